// round 8
// baseline (speedup 1.0000x reference)
#include <cuda_runtime.h>
#include <cuda_bf16.h>
#include <math.h>

// Problem constants
constexpr int BATCH = 4;
constexpr int CIN   = 128;
constexpr int COUT  = 64;
constexpr int HH    = 128;
constexpr int WW    = 128;
constexpr int HWSZ  = HH * WW;
constexpr int DG    = 16;
constexpr int KK    = 9;

// Scratch (static device buffers; allocation APIs are forbidden)
__device__ float g_t1[(size_t)BATCH * COUT * HWSZ];
__device__ float g_t2[(size_t)BATCH * COUT * HWSZ];
__device__ float g_o4[(size_t)BATCH * (27 * DG) * HWSZ];      // 432 channels
__device__ __align__(16) float g_wt[(size_t)CIN * KK * COUT]; // transposed deform weight [cin][k][o]

// ---------------------------------------------------------------------------
// Packed f32x2 helpers (sm_103a FFMA2 path)
// ---------------------------------------------------------------------------
typedef unsigned long long u64;

__device__ __forceinline__ u64 ffma2(u64 a, u64 b, u64 c) {
    u64 d;
    asm("fma.rn.f32x2 %0, %1, %2, %3;" : "=l"(d) : "l"(a), "l"(b), "l"(c));
    return d;
}
__device__ __forceinline__ u64 pk2(float lo, float hi) {
    u64 r;
    asm("mov.b64 %0, {%1, %2};" : "=l"(r) : "f"(lo), "f"(hi));
    return r;
}
__device__ __forceinline__ float2 upk(u64 v) {
    float2 r;
    asm("mov.b64 {%0, %1}, %2;" : "=f"(r.x), "=f"(r.y) : "l"(v));
    return r;
}

// ---------------------------------------------------------------------------
// Transpose deform weight (COUT, CIN, 3, 3) -> [cin][k][o]
// ---------------------------------------------------------------------------
__global__ void transpose_weight_k(const float* __restrict__ w, float* __restrict__ wt) {
    int idx = blockIdx.x * blockDim.x + threadIdx.x;
    int n = CIN * KK * COUT;
    if (idx >= n) return;
    int o   = idx % COUT;
    int k   = (idx / COUT) % KK;
    int cin = idx / (COUT * KK);
    wt[idx] = w[((size_t)o * CIN + cin) * KK + k];
}

// ---------------------------------------------------------------------------
// Direct 3x3 conv, pad=1, stride=1, optional leaky-relu(0.1).
// v3: 256-thread CTAs for occupancy 3 (24 warps/SM vs 16 before).
// Tile: 128 wide x 8 rows x 8 oc (same as before, same grid), but thread =
// 4 px x ONE row x 8 oc -> acc = 16 u64 (32 regs), window held 5 u64 at a
// time (loaded per input row r inside the loop) -> ~70 regs/thread.
// Two phase-shifted smem copies (E/O) keep every sliding pair an aligned
// LDS.64. Two input channels per double-buffered stage.
// grid = (H/8, Cout/8, B), blockDim = (32,8).
// ---------------------------------------------------------------------------
__global__ void __launch_bounds__(256, 3)
conv3x3_k(const float* __restrict__ in, const float* __restrict__ wgt,
          const float* __restrict__ bias, float* __restrict__ out,
          int Cin, int Cout_, int lrelu) {
    const int tx   = threadIdx.x;        // 0..31
    const int ty   = threadIdx.y;        // 0..7  (output row within tile)
    const int tid  = ty * 32 + tx;
    const int lane = tid & 31;
    const int warp = tid >> 5;
    const int y0   = blockIdx.x * 8;
    const int oc0  = blockIdx.y * 8;
    const int b    = blockIdx.z;
    const int px0  = tx * 4;

    __shared__ __align__(16) float s_E[2][2][10][132];  // [buf][ch][row][pos]
    __shared__ __align__(16) float s_O[2][2][10][132];  // shifted +1 copy
    __shared__ __align__(16) u64   s_w[2][2][9][8];     // [buf][ch][k][o] dup-packed

    // permanent zero pads in O copies (col -1 and col 128 are always OOB)
    for (int i = tid; i < 40; i += 256) {
        int bu = i / 20, ch = (i / 10) % 2, t = i % 10;
        s_O[bu][ch][t][0]   = 0.f;
        s_O[bu][ch][t][129] = 0.f;
    }

    u64 acc[8][2];                       // [oc][pxpair]
#pragma unroll
    for (int o = 0; o < 8; o++) { acc[o][0] = 0ull; acc[o][1] = 0ull; }

    const float* inb = in + (size_t)b * Cin * HWSZ;

    auto load_stage = [&](int buf, int ci) {
        // 20 (ch,row) slices over 8 warps
        for (int rr = warp; rr < 20; rr += 8) {
            int ch = rr / 10, t = rr % 10;
            int gy = y0 - 1 + t;
            float4 v = make_float4(0.f, 0.f, 0.f, 0.f);
            if (gy >= 0 && gy < HH) {
                const float* src = inb + (size_t)(ci + ch) * HWSZ + gy * WW;
                v = ((const float4*)src)[lane];
            }
            *((float4*)&s_E[buf][ch][t][lane * 4]) = v;
            float* dO = &s_O[buf][ch][t][lane * 4 + 1];
            dO[0] = v.x; dO[1] = v.y; dO[2] = v.z; dO[3] = v.w;
        }
        if (tid < 144) {
            int ch = tid / 72, r = tid % 72;
            int k = r / 8, o = r % 8;
            float w = wgt[((size_t)(oc0 + o) * Cin + ci + ch) * 9 + k];
            s_w[buf][ch][k][o] = pk2(w, w);
        }
    };

    load_stage(0, 0);
    __syncthreads();

    for (int ci = 0; ci < Cin; ci += 2) {
        const int buf = (ci >> 1) & 1;
        if (ci + 2 < Cin) load_stage(buf ^ 1, ci + 2);

#pragma unroll
        for (int ch = 0; ch < 2; ch++) {
#pragma unroll
            for (int r = 0; r < 3; r++) {
                // input row for this tap row: tile row t = ty + r
                const u64* rowE = (const u64*)&s_E[buf][ch][ty + r][px0];
                const u64* rowO = (const u64*)&s_O[buf][ch][ty + r][px0];
                u64 p0 = rowO[0];   // pair starting px0-1
                u64 p1 = rowE[0];   // pair starting px0
                u64 p2 = rowO[1];   // pair starting px0+1
                u64 p3 = rowE[1];   // pair starting px0+2
                u64 p4 = rowO[2];   // pair starting px0+3
#pragma unroll
                for (int s = 0; s < 3; s++) {
                    const int k = r * 3 + s;
                    u64 a_lo = (s == 0) ? p0 : ((s == 1) ? p1 : p2);
                    u64 a_hi = (s == 0) ? p2 : ((s == 1) ? p3 : p4);
                    const ulonglong2* wk = (const ulonglong2*)&s_w[buf][ch][k][0];
#pragma unroll
                    for (int op = 0; op < 4; op++) {
                        ulonglong2 wq = wk[op];
                        acc[2 * op + 0][0] = ffma2(a_lo, wq.x, acc[2 * op + 0][0]);
                        acc[2 * op + 0][1] = ffma2(a_hi, wq.x, acc[2 * op + 0][1]);
                        acc[2 * op + 1][0] = ffma2(a_lo, wq.y, acc[2 * op + 1][0]);
                        acc[2 * op + 1][1] = ffma2(a_hi, wq.y, acc[2 * op + 1][1]);
                    }
                }
            }
        }
        __syncthreads();
    }

    // store with bias (+ optional leaky relu)
    const int yy = y0 + ty;
#pragma unroll
    for (int o = 0; o < 8; o++) {
        float bv = bias[oc0 + o];
        float* op = out + ((size_t)b * Cout_ + oc0 + o) * HWSZ + yy * WW + px0;
#pragma unroll
        for (int jp = 0; jp < 2; jp++) {
            float2 v = upk(acc[o][jp]);
            v.x += bv; v.y += bv;
            if (lrelu) {
                v.x = (v.x >= 0.f) ? v.x : 0.1f * v.x;
                v.y = (v.y >= 0.f) ? v.y : 0.1f * v.y;
            }
            ((float2*)op)[jp] = v;
        }
    }
}

// ---------------------------------------------------------------------------
// Deformable conv — exact R4 version (best measured config).
// Thread = one pixel, 64 oc accumulators packed as 32 f32x2.
// blockDim = (32,4); grid = (W/32, H/4, B)
// ---------------------------------------------------------------------------
__global__ void __launch_bounds__(128, 4)
deform_k(const float* __restrict__ x, const float* __restrict__ o4,
         const float* __restrict__ wt, const float* __restrict__ bias,
         float* __restrict__ out) {
    const int tx = threadIdx.x, ty = threadIdx.y;
    const int tid = ty * 32 + tx;
    const int b   = blockIdx.z;
    const int px  = blockIdx.x * 32 + tx;
    const int py  = blockIdx.y * 4 + ty;
    const int p   = py * WW + px;

    __shared__ __align__(16) u64 s_w[8 * 9 * 32];  // [c][k][oc-pair]

    u64 acc[32];
#pragma unroll
    for (int q = 0; q < 32; q++) acc[q] = 0ull;

    const float* xb = x + (size_t)b * CIN * HWSZ;
    const float* ob = o4 + (size_t)b * (27 * DG) * HWSZ;

    for (int g = 0; g < DG; g++) {
        __syncthreads();
        const u64* wg = (const u64*)(wt + (size_t)g * 8 * 9 * 64);
        for (int i = tid; i < 8 * 9 * 32; i += 128) s_w[i] = wg[i];
        __syncthreads();

        const float* xg = xb + (size_t)g * 8 * HWSZ;

        for (int k = 0; k < KK; k++) {
            float dy = 10.f * tanhf(ob[(size_t)(g * 18 + 2 * k) * HWSZ + p]);
            float dx = 10.f * tanhf(ob[(size_t)(g * 18 + 2 * k + 1) * HWSZ + p]);
            float mv = ob[(size_t)(288 + g * 9 + k) * HWSZ + p];
            float m  = 1.f / (1.f + __expf(-mv));

            float fy = (float)py - 1.f + (float)(k / 3) + dy;
            float fx = (float)px - 1.f + (float)(k % 3) + dx;
            float y0f = floorf(fy), x0f = floorf(fx);
            float ly = fy - y0f, lx = fx - x0f;
            int y0 = (int)y0f, x0 = (int)x0f;
            int y1 = y0 + 1, x1 = x0 + 1;

            bool vy0 = (y0 >= 0) && (y0 < HH);
            bool vy1 = (y1 >= 0) && (y1 < HH);
            bool vx0 = (x0 >= 0) && (x0 < WW);
            bool vx1 = (x1 >= 0) && (x1 < WW);

            float w00 = (1.f - ly) * (1.f - lx) * ((vy0 && vx0) ? m : 0.f);
            float w01 = (1.f - ly) * lx         * ((vy0 && vx1) ? m : 0.f);
            float w10 = ly * (1.f - lx)         * ((vy1 && vx0) ? m : 0.f);
            float w11 = ly * lx                 * ((vy1 && vx1) ? m : 0.f);

            int yc0 = min(max(y0, 0), HH - 1);
            int yc1 = min(max(y1, 0), HH - 1);
            int xc0 = min(max(x0, 0), WW - 1);
            int xc1 = min(max(x1, 0), WW - 1);
            int i00 = yc0 * WW + xc0, i01 = yc0 * WW + xc1;
            int i10 = yc1 * WW + xc0, i11 = yc1 * WW + xc1;

#pragma unroll
            for (int c = 0; c < 8; c++) {
                const float* xc = xg + (size_t)c * HWSZ;
                float v = w00 * xc[i00] + w01 * xc[i01] + w10 * xc[i10] + w11 * xc[i11];
                u64 v2 = pk2(v, v);
                const ulonglong2* wp = (const ulonglong2*)&s_w[(c * 9 + k) * 32];
#pragma unroll
                for (int q = 0; q < 16; q++) {
                    ulonglong2 wq = wp[q];
                    acc[q * 2 + 0] = ffma2(v2, wq.x, acc[q * 2 + 0]);
                    acc[q * 2 + 1] = ffma2(v2, wq.y, acc[q * 2 + 1]);
                }
            }
        }
    }

    float* outb = out + (size_t)b * COUT * HWSZ + p;
#pragma unroll
    for (int q = 0; q < 32; q++) {
        float2 v = upk(acc[q]);
        outb[(size_t)(2 * q + 0) * HWSZ] = v.x + bias[2 * q + 0];
        outb[(size_t)(2 * q + 1) * HWSZ] = v.y + bias[2 * q + 1];
    }
}

// ---------------------------------------------------------------------------
// Launcher
// ---------------------------------------------------------------------------
extern "C" void kernel_launch(void* const* d_in, const int* in_sizes, int n_in,
                              void* d_out, int out_size) {
    const float* x          = (const float*)d_in[0];
    const float* extra_feat = (const float*)d_in[1];
    const float* w1 = (const float*)d_in[2];
    const float* b1 = (const float*)d_in[3];
    const float* w2 = (const float*)d_in[4];
    const float* b2 = (const float*)d_in[5];
    const float* w3 = (const float*)d_in[6];
    const float* b3 = (const float*)d_in[7];
    const float* w4 = (const float*)d_in[8];
    const float* b4 = (const float*)d_in[9];
    const float* weight = (const float*)d_in[10];
    const float* bias   = (const float*)d_in[11];
    float* out = (float*)d_out;

    float *t1, *t2, *o4, *wt;
    cudaGetSymbolAddress((void**)&t1, g_t1);
    cudaGetSymbolAddress((void**)&t2, g_t2);
    cudaGetSymbolAddress((void**)&o4, g_o4);
    cudaGetSymbolAddress((void**)&wt, g_wt);

    dim3 cblk(32, 8);   // conv: 256 threads
    dim3 dblk(32, 4);   // deform: 128 threads

    // Transpose deform weight (only consumer is deform_k, last kernel)
    {
        int n = CIN * KK * COUT;
        transpose_weight_k<<<(n + 255) / 256, 256>>>(weight, wt);
    }

    // conv1: extra_feat (192ch) -> t1 (64ch), lrelu
    conv3x3_k<<<dim3(HH / 8, COUT / 8, BATCH), cblk>>>(extra_feat, w1, b1, t1, 3 * COUT, COUT, 1);
    // conv2: t1 -> t2, lrelu
    conv3x3_k<<<dim3(HH / 8, COUT / 8, BATCH), cblk>>>(t1, w2, b2, t2, COUT, COUT, 1);
    // conv3: t2 -> t1, lrelu
    conv3x3_k<<<dim3(HH / 8, COUT / 8, BATCH), cblk>>>(t2, w3, b3, t1, COUT, COUT, 1);
    // conv4: t1 -> o4 (432ch), no activation (fused into deform)
    conv3x3_k<<<dim3(HH / 8, (27 * DG) / 8, BATCH), cblk>>>(t1, w4, b4, o4, COUT, 27 * DG, 0);
    // deformable conv: x + o4 -> out
    deform_k<<<dim3(WW / 32, HH / 4, BATCH), dblk>>>(x, o4, wt, bias, out);
}

// round 10
// speedup vs baseline: 1.0760x; 1.0760x over previous
#include <cuda_runtime.h>
#include <cuda_bf16.h>
#include <math.h>

// Problem constants
constexpr int BATCH = 4;
constexpr int CIN   = 128;
constexpr int COUT  = 64;
constexpr int HH    = 128;
constexpr int WW    = 128;
constexpr int HWSZ  = HH * WW;
constexpr int DG    = 16;
constexpr int KK    = 9;

// Scratch (static device buffers; allocation APIs are forbidden)
__device__ float g_t1[(size_t)BATCH * COUT * HWSZ];
__device__ float g_t2[(size_t)BATCH * COUT * HWSZ];
__device__ float g_o4[(size_t)BATCH * (27 * DG) * HWSZ];      // 432 channels
__device__ __align__(16) float g_wt[(size_t)CIN * KK * COUT]; // transposed deform weight [cin][k][o]

// ---------------------------------------------------------------------------
// Packed f32x2 helpers (sm_103a FFMA2 path)
// ---------------------------------------------------------------------------
typedef unsigned long long u64;

__device__ __forceinline__ u64 ffma2(u64 a, u64 b, u64 c) {
    u64 d;
    asm("fma.rn.f32x2 %0, %1, %2, %3;" : "=l"(d) : "l"(a), "l"(b), "l"(c));
    return d;
}
__device__ __forceinline__ u64 pk2(float lo, float hi) {
    u64 r;
    asm("mov.b64 %0, {%1, %2};" : "=l"(r) : "f"(lo), "f"(hi));
    return r;
}
__device__ __forceinline__ float2 upk(u64 v) {
    float2 r;
    asm("mov.b64 {%0, %1}, %2;" : "=f"(r.x), "=f"(r.y) : "l"(v));
    return r;
}
__device__ __forceinline__ float fast_tanh(float x) {
    return 1.f - 2.f / (__expf(2.f * x) + 1.f);
}
__device__ __forceinline__ float fast_sigmoid(float x) {
    return 1.f / (1.f + __expf(-x));
}

// ---------------------------------------------------------------------------
// Transpose deform weight (COUT, CIN, 3, 3) -> [cin][k][o]
// ---------------------------------------------------------------------------
__global__ void transpose_weight_k(const float* __restrict__ w, float* __restrict__ wt) {
    int idx = blockIdx.x * blockDim.x + threadIdx.x;
    int n = CIN * KK * COUT;
    if (idx >= n) return;
    int o   = idx % COUT;
    int k   = (idx / COUT) % KK;
    int cin = idx / (COUT * KK);
    wt[idx] = w[((size_t)o * CIN + cin) * KK + k];
}

// ---------------------------------------------------------------------------
// Direct 3x3 conv v4: bank-conflict-free sliding pairs.
// Thread pixels = two strided PAIRS: cols (2tx, 2tx+1) and (64+2tx, 64+2tx+1),
// rows ty*2, ty*2+1. All sliding-pair LDS.64 are at 8-byte lane stride
// (2-phase natural, no 4-way conflicts of the old 16B-stride layout).
//   E[t][c]   = input col c          (pairs starting at even col)
//   O[t][pos] = input col pos-1      (pairs starting at odd col; 0/129 pad)
// Weights [ch][k][o] dup-packed; 1 broadcast LDS.128 feeds 2 oc x 4 FFMA2.
// Double-buffered, 2 input channels per stage, 1 barrier per stage.
// grid = (H/8, Cout/8, B), blockDim = (32,4).
// ---------------------------------------------------------------------------
__global__ void __launch_bounds__(128, 4)
conv3x3_k(const float* __restrict__ in, const float* __restrict__ wgt,
          const float* __restrict__ bias, float* __restrict__ out,
          int Cin, int Cout_, int lrelu) {
    const int tx   = threadIdx.x;        // 0..31
    const int ty   = threadIdx.y;        // 0..3
    const int tid  = ty * 32 + tx;
    const int lane = tid & 31;
    const int warp = tid >> 5;
    const int y0   = blockIdx.x * 8;
    const int oc0  = blockIdx.y * 8;
    const int b    = blockIdx.z;

    __shared__ __align__(16) float s_E[2][2][10][128];  // [buf][ch][row][col]
    __shared__ __align__(16) float s_O[2][2][10][132];  // shifted +1 copy
    __shared__ __align__(16) u64   s_w[2][2][9][8];     // [buf][ch][k][o] dup-packed

    // permanent zero pads in O copies (col -1 and col 128 are always OOB)
    for (int i = tid; i < 40; i += 128) {
        int bu = i / 20, ch = (i / 10) % 2, t = i % 10;
        s_O[bu][ch][t][0]   = 0.f;
        s_O[bu][ch][t][129] = 0.f;
    }

    u64 acc[2][8][2];                    // [half][oc][row]
#pragma unroll
    for (int h = 0; h < 2; h++)
#pragma unroll
        for (int o = 0; o < 8; o++) { acc[h][o][0] = 0ull; acc[h][o][1] = 0ull; }

    const float* inb = in + (size_t)b * Cin * HWSZ;

    auto load_stage = [&](int buf, int ci) {
#pragma unroll
        for (int rr = warp; rr < 20; rr += 4) {
            int ch = rr / 10, t = rr % 10;
            int gy = y0 - 1 + t;
            float4 v = make_float4(0.f, 0.f, 0.f, 0.f);
            if (gy >= 0 && gy < HH) {
                const float* src = inb + (size_t)(ci + ch) * HWSZ + gy * WW;
                v = ((const float4*)src)[lane];
            }
            *((float4*)&s_E[buf][ch][t][lane * 4]) = v;
            float* dO = &s_O[buf][ch][t][1 + lane * 4];
            dO[0] = v.x; dO[1] = v.y; dO[2] = v.z; dO[3] = v.w;
        }
        for (int i = tid; i < 144; i += 128) {
            int ch = i / 72, r = i % 72;
            int k = r / 8, o = r % 8;
            float w = wgt[((size_t)(oc0 + o) * Cin + ci + ch) * 9 + k];
            s_w[buf][ch][k][o] = pk2(w, w);
        }
    };

    load_stage(0, 0);
    __syncthreads();

    for (int ci = 0; ci < Cin; ci += 2) {
        const int buf = (ci >> 1) & 1;
        if (ci + 2 < Cin) load_stage(buf ^ 1, ci + 2);

#pragma unroll
        for (int ch = 0; ch < 2; ch++) {
#pragma unroll
            for (int half = 0; half < 2; half++) {
                const int cb  = half * 64 + 2 * tx;   // pair start col
                const int u   = cb >> 1;              // u64 index
                // p[q][s]: input pair starting at col cb-1+s, tile row ty*2+q
                u64 p[4][3];
#pragma unroll
                for (int q = 0; q < 4; q++) {
                    const u64* rowE = (const u64*)&s_E[buf][ch][ty * 2 + q][0];
                    const u64* rowO = (const u64*)&s_O[buf][ch][ty * 2 + q][0];
                    p[q][0] = rowO[u];       // pair starting cb-1
                    p[q][1] = rowE[u];       // pair starting cb
                    p[q][2] = rowO[u + 1];   // pair starting cb+1
                }
#pragma unroll
                for (int k = 0; k < 9; k++) {
                    const int r = k / 3, s = k % 3;
                    const ulonglong2* wk = (const ulonglong2*)&s_w[buf][ch][k][0];
#pragma unroll
                    for (int op = 0; op < 4; op++) {
                        ulonglong2 wq = wk[op];
                        const int o0 = 2 * op, o1 = 2 * op + 1;
                        acc[half][o0][0] = ffma2(p[r + 0][s], wq.x, acc[half][o0][0]);
                        acc[half][o0][1] = ffma2(p[r + 1][s], wq.x, acc[half][o0][1]);
                        acc[half][o1][0] = ffma2(p[r + 0][s], wq.y, acc[half][o1][0]);
                        acc[half][o1][1] = ffma2(p[r + 1][s], wq.y, acc[half][o1][1]);
                    }
                }
            }
        }
        __syncthreads();
    }

    // store with bias (+ optional leaky relu)
#pragma unroll
    for (int o = 0; o < 8; o++) {
        float bv = bias[oc0 + o];
#pragma unroll
        for (int i = 0; i < 2; i++) {
            int yy = y0 + ty * 2 + i;
            float* op = out + ((size_t)b * Cout_ + oc0 + o) * HWSZ + yy * WW;
#pragma unroll
            for (int half = 0; half < 2; half++) {
                const int cb = half * 64 + 2 * tx;
                float2 v = upk(acc[half][o][i]);
                v.x += bv; v.y += bv;
                if (lrelu) {
                    v.x = (v.x >= 0.f) ? v.x : 0.1f * v.x;
                    v.y = (v.y >= 0.f) ? v.y : 0.1f * v.y;
                }
                *((float2*)&op[cb]) = v;
            }
        }
    }
}

// ---------------------------------------------------------------------------
// Deformable conv — R4 best version (+ fast activations, numerically verified).
// Thread = one pixel, 64 oc accumulators packed as 32 f32x2.
// blockDim = (32,4); grid = (W/32, H/4, B)
// ---------------------------------------------------------------------------
__global__ void __launch_bounds__(128, 4)
deform_k(const float* __restrict__ x, const float* __restrict__ o4,
         const float* __restrict__ wt, const float* __restrict__ bias,
         float* __restrict__ out) {
    const int tx = threadIdx.x, ty = threadIdx.y;
    const int tid = ty * 32 + tx;
    const int b   = blockIdx.z;
    const int px  = blockIdx.x * 32 + tx;
    const int py  = blockIdx.y * 4 + ty;
    const int p   = py * WW + px;

    __shared__ __align__(16) u64 s_w[8 * 9 * 32];  // [c][k][oc-pair]

    u64 acc[32];
#pragma unroll
    for (int q = 0; q < 32; q++) acc[q] = 0ull;

    const float* xb = x + (size_t)b * CIN * HWSZ;
    const float* ob = o4 + (size_t)b * (27 * DG) * HWSZ;

    for (int g = 0; g < DG; g++) {
        __syncthreads();
        const u64* wg = (const u64*)(wt + (size_t)g * 8 * 9 * 64);
        for (int i = tid; i < 8 * 9 * 32; i += 128) s_w[i] = wg[i];
        __syncthreads();

        const float* xg = xb + (size_t)g * 8 * HWSZ;

        for (int k = 0; k < KK; k++) {
            float dy = 10.f * fast_tanh(ob[(size_t)(g * 18 + 2 * k) * HWSZ + p]);
            float dx = 10.f * fast_tanh(ob[(size_t)(g * 18 + 2 * k + 1) * HWSZ + p]);
            float m  = fast_sigmoid(ob[(size_t)(288 + g * 9 + k) * HWSZ + p]);

            float fy = (float)py - 1.f + (float)(k / 3) + dy;
            float fx = (float)px - 1.f + (float)(k % 3) + dx;
            float y0f = floorf(fy), x0f = floorf(fx);
            float ly = fy - y0f, lx = fx - x0f;
            int y0 = (int)y0f, x0 = (int)x0f;
            int y1 = y0 + 1, x1 = x0 + 1;

            bool vy0 = (y0 >= 0) && (y0 < HH);
            bool vy1 = (y1 >= 0) && (y1 < HH);
            bool vx0 = (x0 >= 0) && (x0 < WW);
            bool vx1 = (x1 >= 0) && (x1 < WW);

            float w00 = (1.f - ly) * (1.f - lx) * ((vy0 && vx0) ? m : 0.f);
            float w01 = (1.f - ly) * lx         * ((vy0 && vx1) ? m : 0.f);
            float w10 = ly * (1.f - lx)         * ((vy1 && vx0) ? m : 0.f);
            float w11 = ly * lx                 * ((vy1 && vx1) ? m : 0.f);

            int yc0 = min(max(y0, 0), HH - 1);
            int yc1 = min(max(y1, 0), HH - 1);
            int xc0 = min(max(x0, 0), WW - 1);
            int xc1 = min(max(x1, 0), WW - 1);
            int i00 = yc0 * WW + xc0, i01 = yc0 * WW + xc1;
            int i10 = yc1 * WW + xc0, i11 = yc1 * WW + xc1;

#pragma unroll
            for (int c = 0; c < 8; c++) {
                const float* xc = xg + (size_t)c * HWSZ;
                float v = w00 * xc[i00] + w01 * xc[i01] + w10 * xc[i10] + w11 * xc[i11];
                u64 v2 = pk2(v, v);
                const ulonglong2* wp = (const ulonglong2*)&s_w[(c * 9 + k) * 32];
#pragma unroll
                for (int q = 0; q < 16; q++) {
                    ulonglong2 wq = wp[q];
                    acc[q * 2 + 0] = ffma2(v2, wq.x, acc[q * 2 + 0]);
                    acc[q * 2 + 1] = ffma2(v2, wq.y, acc[q * 2 + 1]);
                }
            }
        }
    }

    float* outb = out + (size_t)b * COUT * HWSZ + p;
#pragma unroll
    for (int q = 0; q < 32; q++) {
        float2 v = upk(acc[q]);
        outb[(size_t)(2 * q + 0) * HWSZ] = v.x + bias[2 * q + 0];
        outb[(size_t)(2 * q + 1) * HWSZ] = v.y + bias[2 * q + 1];
    }
}

// ---------------------------------------------------------------------------
// Launcher (single stream — stream/event creation violates the alloc guard)
// ---------------------------------------------------------------------------
extern "C" void kernel_launch(void* const* d_in, const int* in_sizes, int n_in,
                              void* d_out, int out_size) {
    const float* x          = (const float*)d_in[0];
    const float* extra_feat = (const float*)d_in[1];
    const float* w1 = (const float*)d_in[2];
    const float* b1 = (const float*)d_in[3];
    const float* w2 = (const float*)d_in[4];
    const float* b2 = (const float*)d_in[5];
    const float* w3 = (const float*)d_in[6];
    const float* b3 = (const float*)d_in[7];
    const float* w4 = (const float*)d_in[8];
    const float* b4 = (const float*)d_in[9];
    const float* weight = (const float*)d_in[10];
    const float* bias   = (const float*)d_in[11];
    float* out = (float*)d_out;

    float *t1, *t2, *o4, *wt;
    cudaGetSymbolAddress((void**)&t1, g_t1);
    cudaGetSymbolAddress((void**)&t2, g_t2);
    cudaGetSymbolAddress((void**)&o4, g_o4);
    cudaGetSymbolAddress((void**)&wt, g_wt);

    dim3 blk(32, 4);

    // Transpose deform weight (only consumer is deform_k, last kernel)
    {
        int n = CIN * KK * COUT;
        transpose_weight_k<<<(n + 255) / 256, 256>>>(weight, wt);
    }

    // conv1: extra_feat (192ch) -> t1 (64ch), lrelu
    conv3x3_k<<<dim3(HH / 8, COUT / 8, BATCH), blk>>>(extra_feat, w1, b1, t1, 3 * COUT, COUT, 1);
    // conv2: t1 -> t2, lrelu
    conv3x3_k<<<dim3(HH / 8, COUT / 8, BATCH), blk>>>(t1, w2, b2, t2, COUT, COUT, 1);
    // conv3: t2 -> t1, lrelu
    conv3x3_k<<<dim3(HH / 8, COUT / 8, BATCH), blk>>>(t2, w3, b3, t1, COUT, COUT, 1);
    // conv4: t1 -> o4 (432ch), no activation (fused into deform)
    conv3x3_k<<<dim3(HH / 8, (27 * DG) / 8, BATCH), blk>>>(t1, w4, b4, o4, COUT, 27 * DG, 0);
    // deformable conv: x + o4 -> out
    deform_k<<<dim3(WW / 32, HH / 4, BATCH), blk>>>(x, o4, wt, bias, out);
}

// round 12
// speedup vs baseline: 1.3671x; 1.2706x over previous
#include <cuda_runtime.h>
#include <cuda_bf16.h>
#include <math.h>
#include <stdint.h>

// Problem constants
constexpr int BATCH = 4;
constexpr int CIN   = 128;
constexpr int COUT  = 64;
constexpr int HH    = 128;
constexpr int WW    = 128;
constexpr int HWSZ  = HH * WW;
constexpr int DG    = 16;
constexpr int KK    = 9;
constexpr int OC4   = 27 * DG;   // 432
constexpr int OCP   = 512;       // padded oc for conv4 MMA

// Scratch (static device buffers; allocation APIs are forbidden)
__device__ float g_t1[(size_t)BATCH * COUT * HWSZ];
__device__ float g_t2[(size_t)BATCH * COUT * HWSZ];
__device__ float g_o4[(size_t)BATCH * OC4 * HWSZ];
__device__ __align__(16) float g_wt[(size_t)CIN * KK * COUT];       // deform weight [cin][k][o]
__device__ __align__(16) __nv_bfloat16 g_w4h[(size_t)9 * OCP * 64]; // conv4 weight hi [k][oc][cin]
__device__ __align__(16) __nv_bfloat16 g_w4l[(size_t)9 * OCP * 64]; // conv4 weight lo

// ---------------------------------------------------------------------------
// Packed f32x2 helpers (sm_103a FFMA2 path)
// ---------------------------------------------------------------------------
typedef unsigned long long u64;

__device__ __forceinline__ u64 ffma2(u64 a, u64 b, u64 c) {
    u64 d;
    asm("fma.rn.f32x2 %0, %1, %2, %3;" : "=l"(d) : "l"(a), "l"(b), "l"(c));
    return d;
}
__device__ __forceinline__ u64 pk2(float lo, float hi) {
    u64 r;
    asm("mov.b64 %0, {%1, %2};" : "=l"(r) : "f"(lo), "f"(hi));
    return r;
}
__device__ __forceinline__ float2 upk(u64 v) {
    float2 r;
    asm("mov.b64 {%0, %1}, %2;" : "=f"(r.x), "=f"(r.y) : "l"(v));
    return r;
}
__device__ __forceinline__ float fast_tanh(float x) {
    return 1.f - 2.f / (__expf(2.f * x) + 1.f);
}
__device__ __forceinline__ float fast_sigmoid(float x) {
    return 1.f / (1.f + __expf(-x));
}
__device__ __forceinline__ uint32_t smem_u32(const void* p) {
    uint32_t a;
    asm("{ .reg .u64 t; cvta.to.shared.u64 t, %1; cvt.u32.u64 %0, t; }" : "=r"(a) : "l"(p));
    return a;
}

// ---------------------------------------------------------------------------
// HMMA helpers (base-target instructions: sm_80+, legal on compute_103)
// ---------------------------------------------------------------------------
__device__ __forceinline__ void ldsm_x4(uint32_t& r0, uint32_t& r1,
                                        uint32_t& r2, uint32_t& r3, uint32_t addr) {
    asm volatile("ldmatrix.sync.aligned.m8n8.x4.shared.b16 {%0,%1,%2,%3}, [%4];"
                 : "=r"(r0), "=r"(r1), "=r"(r2), "=r"(r3) : "r"(addr));
}
__device__ __forceinline__ void mma16816(float* d, const uint32_t* a,
                                         uint32_t b0, uint32_t b1) {
    asm volatile(
        "mma.sync.aligned.m16n8k16.row.col.f32.bf16.bf16.f32 "
        "{%0,%1,%2,%3}, {%4,%5,%6,%7}, {%8,%9}, {%0,%1,%2,%3};"
        : "+f"(d[0]), "+f"(d[1]), "+f"(d[2]), "+f"(d[3])
        : "r"(a[0]), "r"(a[1]), "r"(a[2]), "r"(a[3]), "r"(b0), "r"(b1));
}

// ---------------------------------------------------------------------------
// Prep kernels
// ---------------------------------------------------------------------------
__global__ void transpose_weight_k(const float* __restrict__ w, float* __restrict__ wt) {
    int idx = blockIdx.x * blockDim.x + threadIdx.x;
    int n = CIN * KK * COUT;
    if (idx >= n) return;
    int o   = idx % COUT;
    int k   = (idx / COUT) % KK;
    int cin = idx / (COUT * KK);
    wt[idx] = w[((size_t)o * CIN + cin) * KK + k];
}

// Split conv4 weight (432,64,3,3) f32 -> [k][oc padded 512][cin] bf16 hi/lo
__global__ void split_w4_k(const float* __restrict__ w4) {
    int idx = blockIdx.x * blockDim.x + threadIdx.x;
    if (idx >= 9 * OCP * 64) return;
    int c  = idx & 63;
    int oc = (idx >> 6) & (OCP - 1);
    int k  = idx >> 15;
    float v = (oc < OC4) ? w4[((size_t)oc * 64 + c) * 9 + k] : 0.f;
    __nv_bfloat16 h = __float2bfloat16(v);
    float hf = __bfloat162float(h);
    __nv_bfloat16 l = __float2bfloat16(v - hf);
    g_w4h[idx] = h;
    g_w4l[idx] = l;
}

// ---------------------------------------------------------------------------
// Direct 3x3 conv (R4 best version), pad=1, stride=1, opt lrelu(0.1).
// Used for conv1/2/3.
// ---------------------------------------------------------------------------
__global__ void __launch_bounds__(128, 4)
conv3x3_k(const float* __restrict__ in, const float* __restrict__ wgt,
          const float* __restrict__ bias, float* __restrict__ out,
          int Cin, int Cout_, int lrelu) {
    const int tx   = threadIdx.x;
    const int ty   = threadIdx.y;
    const int tid  = ty * 32 + tx;
    const int lane = tid & 31;
    const int warp = tid >> 5;
    const int y0   = blockIdx.x * 8;
    const int oc0  = blockIdx.y * 8;
    const int b    = blockIdx.z;
    const int px0  = tx * 4;

    __shared__ __align__(16) float s_E[2][2][10][132];
    __shared__ __align__(16) float s_O[2][2][10][132];
    __shared__ __align__(16) u64   s_w[2][2][9][8];

    for (int i = tid; i < 40; i += 128) {
        int bu = i / 20, ch = (i / 10) % 2, t = i % 10;
        s_O[bu][ch][t][0]   = 0.f;
        s_O[bu][ch][t][129] = 0.f;
    }

    u64 acc[8][2][2];
#pragma unroll
    for (int o = 0; o < 8; o++)
#pragma unroll
        for (int i = 0; i < 2; i++) { acc[o][i][0] = 0ull; acc[o][i][1] = 0ull; }

    const float* inb = in + (size_t)b * Cin * HWSZ;

    auto load_stage = [&](int buf, int ci) {
#pragma unroll
        for (int rr = warp; rr < 20; rr += 4) {
            int ch = rr / 10, t = rr % 10;
            int gy = y0 - 1 + t;
            float4 v = make_float4(0.f, 0.f, 0.f, 0.f);
            if (gy >= 0 && gy < HH) {
                const float* src = inb + (size_t)(ci + ch) * HWSZ + gy * WW;
                v = ((const float4*)src)[lane];
            }
            *((float4*)&s_E[buf][ch][t][lane * 4]) = v;
            float* dO = &s_O[buf][ch][t][lane * 4 + 1];
            dO[0] = v.x; dO[1] = v.y; dO[2] = v.z; dO[3] = v.w;
        }
        for (int i = tid; i < 144; i += 128) {
            int ch = i / 72, r = i % 72;
            int k = r / 8, o = r % 8;
            float w = wgt[((size_t)(oc0 + o) * Cin + ci + ch) * 9 + k];
            s_w[buf][ch][k][o] = pk2(w, w);
        }
    };

    load_stage(0, 0);
    __syncthreads();

    for (int ci = 0; ci < Cin; ci += 2) {
        const int buf = (ci >> 1) & 1;
        if (ci + 2 < Cin) load_stage(buf ^ 1, ci + 2);

#pragma unroll
        for (int ch = 0; ch < 2; ch++) {
            u64 p[4][5];
#pragma unroll
            for (int r = 0; r < 4; r++) {
                const u64* rowE = (const u64*)&s_E[buf][ch][ty * 2 + r][px0];
                const u64* rowO = (const u64*)&s_O[buf][ch][ty * 2 + r][px0];
                p[r][1] = rowE[0];
                p[r][3] = rowE[1];
                p[r][0] = rowO[0];
                p[r][2] = rowO[1];
                p[r][4] = rowO[2];
            }
#pragma unroll
            for (int k = 0; k < 9; k++) {
                const int r = k / 3, s = k % 3;
                const ulonglong2* wk = (const ulonglong2*)&s_w[buf][ch][k][0];
#pragma unroll
                for (int op = 0; op < 4; op++) {
                    ulonglong2 wq = wk[op];
                    const int o0 = 2 * op, o1 = 2 * op + 1;
                    acc[o0][0][0] = ffma2(p[r + 0][s],     wq.x, acc[o0][0][0]);
                    acc[o0][0][1] = ffma2(p[r + 0][s + 2], wq.x, acc[o0][0][1]);
                    acc[o0][1][0] = ffma2(p[r + 1][s],     wq.x, acc[o0][1][0]);
                    acc[o0][1][1] = ffma2(p[r + 1][s + 2], wq.x, acc[o0][1][1]);
                    acc[o1][0][0] = ffma2(p[r + 0][s],     wq.y, acc[o1][0][0]);
                    acc[o1][0][1] = ffma2(p[r + 0][s + 2], wq.y, acc[o1][0][1]);
                    acc[o1][1][0] = ffma2(p[r + 1][s],     wq.y, acc[o1][1][0]);
                    acc[o1][1][1] = ffma2(p[r + 1][s + 2], wq.y, acc[o1][1][1]);
                }
            }
        }
        __syncthreads();
    }

#pragma unroll
    for (int o = 0; o < 8; o++) {
        float bv = bias[oc0 + o];
#pragma unroll
        for (int i = 0; i < 2; i++) {
            int yy = y0 + ty * 2 + i;
            float* op = out + ((size_t)b * Cout_ + oc0 + o) * HWSZ + yy * WW + px0;
#pragma unroll
            for (int jp = 0; jp < 2; jp++) {
                float2 v = upk(acc[o][i][jp]);
                v.x += bv; v.y += bv;
                if (lrelu) {
                    v.x = (v.x >= 0.f) ? v.x : 0.1f * v.x;
                    v.y = (v.y >= 0.f) ? v.y : 0.1f * v.y;
                }
                ((float2*)op)[jp] = v;
            }
        }
    }
}

// ---------------------------------------------------------------------------
// conv4 via mma.sync (HMMA bf16, split hi/lo for ~fp32 accuracy).
// CTA: one image row y, 128-oc tile. 256 threads / 8 warps.
// Warp w: oc rows [w*16, w*16+16), all 128 px -> 16 m16n8 D tiles.
// 3x3 conv = 9 accumulating GEMM passes over (di,dj); k = cin 64 (4 chunks).
// Input row (y+di) staged TRANSPOSED [px][cin] bf16 hi/lo; weights [oc][cin].
// grid = (128, OCP/128, BATCH) = 2048 CTAs.
// ---------------------------------------------------------------------------
constexpr int LDX = 72;   // bf16 elems per px row (64 + pad)
constexpr int LDW = 72;   // bf16 elems per oc row
constexpr uint32_t SX_H = 0;
constexpr uint32_t SX_L = SX_H + 130 * LDX * 2;       // 18720 -> next
constexpr uint32_t SW_H = SX_L + 130 * LDX * 2;       // 37440
constexpr uint32_t SW_L = SW_H + 128 * LDW * 2;       // 55872
constexpr uint32_t SMEM4 = SW_L + 128 * LDW * 2 + 256; // 74560

__global__ void __launch_bounds__(256, 2)
conv4_mma_k(const float* __restrict__ t1, const float* __restrict__ b4,
            float* __restrict__ o4) {
    extern __shared__ char sm[];
    const uint32_t sbase = smem_u32(sm);

    const int tid  = threadIdx.x;
    const int w    = tid >> 5;
    const int lane = tid & 31;
    const int y = blockIdx.x;
    const int m = blockIdx.y;
    const int b = blockIdx.z;

    __nv_bfloat16* sxh = (__nv_bfloat16*)(sm + SX_H);
    __nv_bfloat16* sxl = (__nv_bfloat16*)(sm + SX_L);
    __nv_bfloat16* swh = (__nv_bfloat16*)(sm + SW_H);
    __nv_bfloat16* swl = (__nv_bfloat16*)(sm + SW_L);

    // zero border px rows (0 and 129) once
    for (int i = tid; i < LDX; i += 256) {
        sxh[i] = __float2bfloat16(0.f);
        sxl[i] = __float2bfloat16(0.f);
        sxh[129 * LDX + i] = __float2bfloat16(0.f);
        sxl[129 * LDX + i] = __float2bfloat16(0.f);
    }

    float d[16][4];
#pragma unroll
    for (int nt = 0; nt < 16; nt++)
#pragma unroll
        for (int j = 0; j < 4; j++) d[nt][j] = 0.f;

    const float* t1b = t1 + (size_t)b * COUT * HWSZ;

    // A fragment smem element offsets (constant per lane, vary by kc)
    const int a_row = w * 16 + (lane & 15);
    const int a_ko  = (lane >> 4) * 8;
    // B fragment: lane -> (ntile half, row-in-8, k half)
    const int b_r   = lane & 7;
    const int b_ko  = ((lane >> 3) & 1) * 8;
    const int b_seg = lane >> 4;

    for (int di = -1; di <= 1; di++) {
        __syncthreads();                       // protect s_x from prior reads
        // stage input row y+di transposed: s_x[1+px][cin], split hi/lo
        {
            const int yy = y + di;
            const bool valid = (yy >= 0) && (yy < HH);
            const float* trow = t1b + (size_t)(valid ? yy : 0) * WW;
            for (int i = tid; i < 64 * 128; i += 256) {
                int c = i >> 7, px = i & 127;
                float v = valid ? trow[(size_t)c * HWSZ + px] : 0.f;
                __nv_bfloat16 h = __float2bfloat16(v);
                float hf = __bfloat162float(h);
                __nv_bfloat16 l = __float2bfloat16(v - hf);
                sxh[(1 + px) * LDX + c] = h;
                sxl[(1 + px) * LDX + c] = l;
            }
        }
        for (int dj = -1; dj <= 1; dj++) {
            const int tap = (di + 1) * 3 + (dj + 1);
            __syncthreads();                   // x visible; protect s_w
            // stage weights for this tap: [128 oc][64 cin] hi/lo
            {
                const size_t base = ((size_t)tap * OCP + m * 128) * 64;
                const uint4* gh = (const uint4*)(g_w4h + base);
                const uint4* gl = (const uint4*)(g_w4l + base);
                for (int i = tid; i < 1024; i += 256) {
                    int ocl = i >> 3, cc = (i & 7) * 8;
                    *(uint4*)&swh[ocl * LDW + cc] = gh[i];
                    *(uint4*)&swl[ocl * LDW + cc] = gl[i];
                }
            }
            __syncthreads();                   // w visible

#pragma unroll
            for (int kc = 0; kc < 4; kc++) {
                uint32_t aH[4], aL[4];
                {
                    uint32_t off = (uint32_t)(a_row * LDW + kc * 16 + a_ko) * 2;
                    ldsm_x4(aH[0], aH[1], aH[2], aH[3], sbase + SW_H + off);
                    ldsm_x4(aL[0], aL[1], aL[2], aL[3], sbase + SW_L + off);
                }
#pragma unroll
                for (int nt2 = 0; nt2 < 8; nt2++) {
                    const int row = 1 + dj + nt2 * 16 + b_seg * 8 + b_r;
                    uint32_t off = (uint32_t)(row * LDX + kc * 16 + b_ko) * 2;
                    uint32_t bh0, bh1, bh2, bh3, bl0, bl1, bl2, bl3;
                    ldsm_x4(bh0, bh1, bh2, bh3, sbase + SX_H + off);
                    ldsm_x4(bl0, bl1, bl2, bl3, sbase + SX_L + off);
                    float* d0 = d[nt2 * 2];
                    float* d1 = d[nt2 * 2 + 1];
                    mma16816(d0, aH, bh0, bh1);   // hi*hi
                    mma16816(d0, aH, bl0, bl1);   // hi*lo
                    mma16816(d0, aL, bh0, bh1);   // lo*hi
                    mma16816(d1, aH, bh2, bh3);
                    mma16816(d1, aH, bl2, bl3);
                    mma16816(d1, aL, bh2, bh3);
                }
            }
        }
    }

    // epilogue: D fragment -> o4 (+bias). d0,d1 = (oc=g, px,px+1); d2,d3 = oc+8.
    const int g   = lane >> 2;
    const int tig = lane & 3;
#pragma unroll
    for (int nt = 0; nt < 16; nt++) {
        int px  = nt * 8 + tig * 2;
        int oc0 = m * 128 + w * 16 + g;
        int oc1 = oc0 + 8;
        size_t rowoff = (size_t)y * WW + px;
        if (oc0 < OC4) {
            float bv = b4[oc0];
            *(float2*)(o4 + ((size_t)b * OC4 + oc0) * HWSZ + rowoff)
                = make_float2(d[nt][0] + bv, d[nt][1] + bv);
        }
        if (oc1 < OC4) {
            float bv = b4[oc1];
            *(float2*)(o4 + ((size_t)b * OC4 + oc1) * HWSZ + rowoff)
                = make_float2(d[nt][2] + bv, d[nt][3] + bv);
        }
    }
}

// ---------------------------------------------------------------------------
// Deformable conv — R4 best version (+ fast activations, verified neutral).
// ---------------------------------------------------------------------------
__global__ void __launch_bounds__(128, 4)
deform_k(const float* __restrict__ x, const float* __restrict__ o4,
         const float* __restrict__ wt, const float* __restrict__ bias,
         float* __restrict__ out) {
    const int tx = threadIdx.x, ty = threadIdx.y;
    const int tid = ty * 32 + tx;
    const int b   = blockIdx.z;
    const int px  = blockIdx.x * 32 + tx;
    const int py  = blockIdx.y * 4 + ty;
    const int p   = py * WW + px;

    __shared__ __align__(16) u64 s_w[8 * 9 * 32];

    u64 acc[32];
#pragma unroll
    for (int q = 0; q < 32; q++) acc[q] = 0ull;

    const float* xb = x + (size_t)b * CIN * HWSZ;
    const float* ob = o4 + (size_t)b * OC4 * HWSZ;

    for (int g = 0; g < DG; g++) {
        __syncthreads();
        const u64* wg = (const u64*)(wt + (size_t)g * 8 * 9 * 64);
        for (int i = tid; i < 8 * 9 * 32; i += 128) s_w[i] = wg[i];
        __syncthreads();

        const float* xg = xb + (size_t)g * 8 * HWSZ;

        for (int k = 0; k < KK; k++) {
            float dy = 10.f * fast_tanh(ob[(size_t)(g * 18 + 2 * k) * HWSZ + p]);
            float dx = 10.f * fast_tanh(ob[(size_t)(g * 18 + 2 * k + 1) * HWSZ + p]);
            float m  = fast_sigmoid(ob[(size_t)(288 + g * 9 + k) * HWSZ + p]);

            float fy = (float)py - 1.f + (float)(k / 3) + dy;
            float fx = (float)px - 1.f + (float)(k % 3) + dx;
            float y0f = floorf(fy), x0f = floorf(fx);
            float ly = fy - y0f, lx = fx - x0f;
            int y0 = (int)y0f, x0 = (int)x0f;
            int y1 = y0 + 1, x1 = x0 + 1;

            bool vy0 = (y0 >= 0) && (y0 < HH);
            bool vy1 = (y1 >= 0) && (y1 < HH);
            bool vx0 = (x0 >= 0) && (x0 < WW);
            bool vx1 = (x1 >= 0) && (x1 < WW);

            float w00 = (1.f - ly) * (1.f - lx) * ((vy0 && vx0) ? m : 0.f);
            float w01 = (1.f - ly) * lx         * ((vy0 && vx1) ? m : 0.f);
            float w10 = ly * (1.f - lx)         * ((vy1 && vx0) ? m : 0.f);
            float w11 = ly * lx                 * ((vy1 && vx1) ? m : 0.f);

            int yc0 = min(max(y0, 0), HH - 1);
            int yc1 = min(max(y1, 0), HH - 1);
            int xc0 = min(max(x0, 0), WW - 1);
            int xc1 = min(max(x1, 0), WW - 1);
            int i00 = yc0 * WW + xc0, i01 = yc0 * WW + xc1;
            int i10 = yc1 * WW + xc0, i11 = yc1 * WW + xc1;

#pragma unroll
            for (int c = 0; c < 8; c++) {
                const float* xc = xg + (size_t)c * HWSZ;
                float v = w00 * xc[i00] + w01 * xc[i01] + w10 * xc[i10] + w11 * xc[i11];
                u64 v2 = pk2(v, v);
                const ulonglong2* wp = (const ulonglong2*)&s_w[(c * 9 + k) * 32];
#pragma unroll
                for (int q = 0; q < 16; q++) {
                    ulonglong2 wq = wp[q];
                    acc[q * 2 + 0] = ffma2(v2, wq.x, acc[q * 2 + 0]);
                    acc[q * 2 + 1] = ffma2(v2, wq.y, acc[q * 2 + 1]);
                }
            }
        }
    }

    float* outb = out + (size_t)b * COUT * HWSZ + p;
#pragma unroll
    for (int q = 0; q < 32; q++) {
        float2 v = upk(acc[q]);
        outb[(size_t)(2 * q + 0) * HWSZ] = v.x + bias[2 * q + 0];
        outb[(size_t)(2 * q + 1) * HWSZ] = v.y + bias[2 * q + 1];
    }
}

// ---------------------------------------------------------------------------
// Launcher
// ---------------------------------------------------------------------------
extern "C" void kernel_launch(void* const* d_in, const int* in_sizes, int n_in,
                              void* d_out, int out_size) {
    const float* x          = (const float*)d_in[0];
    const float* extra_feat = (const float*)d_in[1];
    const float* w1 = (const float*)d_in[2];
    const float* b1 = (const float*)d_in[3];
    const float* w2 = (const float*)d_in[4];
    const float* b2 = (const float*)d_in[5];
    const float* w3 = (const float*)d_in[6];
    const float* b3 = (const float*)d_in[7];
    const float* w4 = (const float*)d_in[8];
    const float* b4 = (const float*)d_in[9];
    const float* weight = (const float*)d_in[10];
    const float* bias   = (const float*)d_in[11];
    float* out = (float*)d_out;

    float *t1, *t2, *o4, *wt;
    cudaGetSymbolAddress((void**)&t1, g_t1);
    cudaGetSymbolAddress((void**)&t2, g_t2);
    cudaGetSymbolAddress((void**)&o4, g_o4);
    cudaGetSymbolAddress((void**)&wt, g_wt);

    cudaFuncSetAttribute(conv4_mma_k, cudaFuncAttributeMaxDynamicSharedMemorySize, SMEM4);

    dim3 blk(32, 4);

    // prep: deform weight transpose + conv4 weight bf16 split
    {
        int n = CIN * KK * COUT;
        transpose_weight_k<<<(n + 255) / 256, 256>>>(weight, wt);
        int n2 = 9 * OCP * 64;
        split_w4_k<<<(n2 + 255) / 256, 256>>>(w4);
    }

    // conv1: extra_feat (192ch) -> t1 (64ch), lrelu
    conv3x3_k<<<dim3(HH / 8, COUT / 8, BATCH), blk>>>(extra_feat, w1, b1, t1, 3 * COUT, COUT, 1);
    // conv2: t1 -> t2, lrelu
    conv3x3_k<<<dim3(HH / 8, COUT / 8, BATCH), blk>>>(t1, w2, b2, t2, COUT, COUT, 1);
    // conv3: t2 -> t1, lrelu
    conv3x3_k<<<dim3(HH / 8, COUT / 8, BATCH), blk>>>(t2, w3, b3, t1, COUT, COUT, 1);
    // conv4 on tensor cores (HMMA): t1 -> o4 (432ch, +bias, no activation)
    conv4_mma_k<<<dim3(HH, OCP / 128, BATCH), 256, SMEM4>>>(t1, b4, o4);
    // deformable conv: x + o4 -> out
    deform_k<<<dim3(WW / 32, HH / 4, BATCH), blk>>>(x, o4, wt, bias, out);
}

// round 13
// speedup vs baseline: 1.8787x; 1.3742x over previous
#include <cuda_runtime.h>
#include <cuda_bf16.h>
#include <math.h>
#include <stdint.h>

// Problem constants
constexpr int BATCH = 4;
constexpr int CIN   = 128;
constexpr int COUT  = 64;
constexpr int HH    = 128;
constexpr int WW    = 128;
constexpr int HWSZ  = HH * WW;
constexpr int DG    = 16;
constexpr int KK    = 9;
constexpr int OC4   = 27 * DG;   // 432
constexpr int OCP4  = 448;       // padded oc for conv4 MMA (28 x 16)

// Scratch (static device buffers; allocation APIs are forbidden)
__device__ float g_t1[(size_t)BATCH * COUT * HWSZ];
__device__ float g_t2[(size_t)BATCH * COUT * HWSZ];
__device__ float g_o4[(size_t)BATCH * OC4 * HWSZ];
__device__ __align__(16) float g_wt[(size_t)CIN * KK * COUT];        // deform weight [cin][k][o]
__device__ __align__(16) __nv_bfloat16 g_w1h[(size_t)9 * 64 * 192];  // conv weights [k][ocp][cin]
__device__ __align__(16) __nv_bfloat16 g_w1l[(size_t)9 * 64 * 192];
__device__ __align__(16) __nv_bfloat16 g_w2h[(size_t)9 * 64 * 64];
__device__ __align__(16) __nv_bfloat16 g_w2l[(size_t)9 * 64 * 64];
__device__ __align__(16) __nv_bfloat16 g_w3h[(size_t)9 * 64 * 64];
__device__ __align__(16) __nv_bfloat16 g_w3l[(size_t)9 * 64 * 64];
__device__ __align__(16) __nv_bfloat16 g_w4h[(size_t)9 * OCP4 * 64];
__device__ __align__(16) __nv_bfloat16 g_w4l[(size_t)9 * OCP4 * 64];

// ---------------------------------------------------------------------------
// Packed f32x2 helpers (sm_103a FFMA2 path)
// ---------------------------------------------------------------------------
typedef unsigned long long u64;

__device__ __forceinline__ u64 ffma2(u64 a, u64 b, u64 c) {
    u64 d;
    asm("fma.rn.f32x2 %0, %1, %2, %3;" : "=l"(d) : "l"(a), "l"(b), "l"(c));
    return d;
}
__device__ __forceinline__ u64 pk2(float lo, float hi) {
    u64 r;
    asm("mov.b64 %0, {%1, %2};" : "=l"(r) : "f"(lo), "f"(hi));
    return r;
}
__device__ __forceinline__ float2 upk(u64 v) {
    float2 r;
    asm("mov.b64 {%0, %1}, %2;" : "=f"(r.x), "=f"(r.y) : "l"(v));
    return r;
}
__device__ __forceinline__ float fast_tanh(float x) {
    return 1.f - 2.f / (__expf(2.f * x) + 1.f);
}
__device__ __forceinline__ float fast_sigmoid(float x) {
    return 1.f / (1.f + __expf(-x));
}
__device__ __forceinline__ uint32_t smem_u32(const void* p) {
    uint32_t a;
    asm("{ .reg .u64 t; cvta.to.shared.u64 t, %1; cvt.u32.u64 %0, t; }" : "=r"(a) : "l"(p));
    return a;
}

// ---------------------------------------------------------------------------
// HMMA helpers (base-target instructions: sm_80+, legal on compute_103)
// ---------------------------------------------------------------------------
__device__ __forceinline__ void ldsm_x4(uint32_t& r0, uint32_t& r1,
                                        uint32_t& r2, uint32_t& r3, uint32_t addr) {
    asm volatile("ldmatrix.sync.aligned.m8n8.x4.shared.b16 {%0,%1,%2,%3}, [%4];"
                 : "=r"(r0), "=r"(r1), "=r"(r2), "=r"(r3) : "r"(addr));
}
__device__ __forceinline__ void mma16816(float* d, const uint32_t* a,
                                         uint32_t b0, uint32_t b1) {
    asm volatile(
        "mma.sync.aligned.m16n8k16.row.col.f32.bf16.bf16.f32 "
        "{%0,%1,%2,%3}, {%4,%5,%6,%7}, {%8,%9}, {%0,%1,%2,%3};"
        : "+f"(d[0]), "+f"(d[1]), "+f"(d[2]), "+f"(d[3])
        : "r"(a[0]), "r"(a[1]), "r"(a[2]), "r"(a[3]), "r"(b0), "r"(b1));
}

// ---------------------------------------------------------------------------
// Prep kernels
// ---------------------------------------------------------------------------
__global__ void transpose_weight_k(const float* __restrict__ w, float* __restrict__ wt) {
    int idx = blockIdx.x * blockDim.x + threadIdx.x;
    int n = CIN * KK * COUT;
    if (idx >= n) return;
    int o   = idx % COUT;
    int k   = (idx / COUT) % KK;
    int cin = idx / (COUT * KK);
    wt[idx] = w[((size_t)o * CIN + cin) * KK + k];
}

// Split conv weight (Cout_real, Cin, 3, 3) f32 -> [k][ocp][cin] bf16 hi/lo
__global__ void split_w_k(const float* __restrict__ w, __nv_bfloat16* __restrict__ h,
                          __nv_bfloat16* __restrict__ l, int Cout_real, int ocp, int Cin) {
    int idx = blockIdx.x * blockDim.x + threadIdx.x;
    int n = 9 * ocp * Cin;
    if (idx >= n) return;
    int c  = idx % Cin;
    int oc = (idx / Cin) % ocp;
    int k  = idx / (Cin * ocp);
    float v = (oc < Cout_real) ? w[((size_t)oc * Cin + c) * 9 + k] : 0.f;
    __nv_bfloat16 hi = __float2bfloat16(v);
    float hf = __bfloat162float(hi);
    h[idx] = hi;
    l[idx] = __float2bfloat16(v - hf);
}

// ---------------------------------------------------------------------------
// Generic 3x3 conv via mma.sync (HMMA bf16, split hi/lo for ~fp32 accuracy).
// CTA: one image row y, 64-oc tile. 256 threads / 8 warps.
// Warp w: oc rows [oc0 + (w&3)*16, +16), px cols [(w>>2)*64, +64) -> 8 tiles.
// Cin handled in 64-wide slabs; per (slab, di): stage x row once + all 3
// dj-tap weights, then 3x4 kc MMA passes.
// grid = (HH, ocp/64, BATCH).
// ---------------------------------------------------------------------------
constexpr int LDX = 72;   // bf16 elems per px row (64 + pad)
constexpr int LDW = 72;   // bf16 elems per oc row
constexpr uint32_t SX_H = 0;
constexpr uint32_t SX_L = SX_H + 130 * LDX * 2;        // 18720
constexpr uint32_t SW_H = SX_L + 130 * LDX * 2;        // 37440
constexpr uint32_t SW_L = SW_H + 3 * 64 * LDW * 2;     // 65088
constexpr uint32_t SMEMC = SW_L + 3 * 64 * LDW * 2 + 64; // 92800

__global__ void __launch_bounds__(256, 2)
conv_mma_k(const float* __restrict__ in,
           const __nv_bfloat16* __restrict__ wh, const __nv_bfloat16* __restrict__ wl,
           const float* __restrict__ bias, float* __restrict__ out,
           int Cin, int ocp, int Cout_real, int lrelu) {
    extern __shared__ char sm[];
    const uint32_t sbase = smem_u32(sm);

    const int tid  = threadIdx.x;
    const int w    = tid >> 5;
    const int lane = tid & 31;
    const int y = blockIdx.x;
    const int m = blockIdx.y;
    const int b = blockIdx.z;
    const int oc0  = m * 64;
    const int w_oc = w & 3;    // 16-oc row group
    const int w_px = w >> 2;   // 64-px col group

    __nv_bfloat16* sxh = (__nv_bfloat16*)(sm + SX_H);
    __nv_bfloat16* sxl = (__nv_bfloat16*)(sm + SX_L);
    __nv_bfloat16* swh = (__nv_bfloat16*)(sm + SW_H);
    __nv_bfloat16* swl = (__nv_bfloat16*)(sm + SW_L);

    // zero border px rows (0 and 129) once
    for (int i = tid; i < LDX; i += 256) {
        sxh[i] = __float2bfloat16(0.f);
        sxl[i] = __float2bfloat16(0.f);
        sxh[129 * LDX + i] = __float2bfloat16(0.f);
        sxl[129 * LDX + i] = __float2bfloat16(0.f);
    }

    float d[8][4];
#pragma unroll
    for (int nt = 0; nt < 8; nt++)
#pragma unroll
        for (int j = 0; j < 4; j++) d[nt][j] = 0.f;

    const float* inb = in + (size_t)b * Cin * HWSZ;

    // fragment lane constants
    const int a_rl = w_oc * 16 + (lane & 15);
    const int a_ko = (lane >> 4) * 8;
    const int b_r  = lane & 7;
    const int b_ko = ((lane >> 3) & 1) * 8;
    const int b_seg = lane >> 4;

    const int nslab = Cin >> 6;
    for (int sl = 0; sl < nslab; sl++) {
        for (int di = -1; di <= 1; di++) {
            __syncthreads();   // protect sx/sw from prior iteration's reads
            // --- stage x row (y+di), slab sl, transposed [px][cin], hi/lo ---
            {
                const int yy = y + di;
                const bool valid = (yy >= 0) && (yy < HH);
                const float* trow = inb + ((size_t)sl * 64) * HWSZ + (size_t)(valid ? yy : 0) * WW;
                for (int i = tid; i < 64 * 128; i += 256) {
                    int c = i >> 7, px = i & 127;
                    float v = valid ? trow[(size_t)c * HWSZ + px] : 0.f;
                    __nv_bfloat16 h = __float2bfloat16(v);
                    float hf = __bfloat162float(h);
                    sxh[(1 + px) * LDX + c] = h;
                    sxl[(1 + px) * LDX + c] = __float2bfloat16(v - hf);
                }
            }
            // --- stage weights for the 3 taps of this di, slab sl ---
            {
                for (int i = tid; i < 3 * 512; i += 256) {
                    int t = i >> 9, r = i & 511;
                    int ocl = r >> 3, cc = (r & 7) * 8;
                    size_t gidx = ((size_t)((di + 1) * 3 + t) * ocp + oc0 + ocl) * Cin
                                + (size_t)sl * 64 + cc;
                    *(uint4*)&swh[(t * 64 + ocl) * LDW + cc] = *(const uint4*)(wh + gidx);
                    *(uint4*)&swl[(t * 64 + ocl) * LDW + cc] = *(const uint4*)(wl + gidx);
                }
            }
            __syncthreads();

#pragma unroll
            for (int djs = 0; djs < 3; djs++) {
#pragma unroll
                for (int kc = 0; kc < 4; kc++) {
                    uint32_t aH[4], aL[4];
                    {
                        uint32_t off = (uint32_t)((djs * 64 + a_rl) * LDW + kc * 16 + a_ko) * 2;
                        ldsm_x4(aH[0], aH[1], aH[2], aH[3], sbase + SW_H + off);
                        ldsm_x4(aL[0], aL[1], aL[2], aL[3], sbase + SW_L + off);
                    }
#pragma unroll
                    for (int nt2 = 0; nt2 < 4; nt2++) {
                        const int row = djs + w_px * 64 + nt2 * 16 + b_seg * 8 + b_r;
                        uint32_t off = (uint32_t)(row * LDX + kc * 16 + b_ko) * 2;
                        uint32_t bh0, bh1, bh2, bh3, bl0, bl1, bl2, bl3;
                        ldsm_x4(bh0, bh1, bh2, bh3, sbase + SX_H + off);
                        ldsm_x4(bl0, bl1, bl2, bl3, sbase + SX_L + off);
                        float* d0 = d[nt2 * 2];
                        float* d1 = d[nt2 * 2 + 1];
                        mma16816(d0, aH, bh0, bh1);
                        mma16816(d0, aH, bl0, bl1);
                        mma16816(d0, aL, bh0, bh1);
                        mma16816(d1, aH, bh2, bh3);
                        mma16816(d1, aH, bl2, bl3);
                        mma16816(d1, aL, bh2, bh3);
                    }
                }
            }
        }
    }

    // epilogue: D fragment -> out (+bias, optional lrelu)
    const int g   = lane >> 2;
    const int tig = lane & 3;
#pragma unroll
    for (int nt = 0; nt < 8; nt++) {
        int px  = w_px * 64 + nt * 8 + tig * 2;
        int o0  = oc0 + w_oc * 16 + g;
        int o1  = o0 + 8;
        size_t rowoff = (size_t)y * WW + px;
        if (o0 < Cout_real) {
            float bv = bias[o0];
            float vx = d[nt][0] + bv, vy = d[nt][1] + bv;
            if (lrelu) {
                vx = (vx >= 0.f) ? vx : 0.1f * vx;
                vy = (vy >= 0.f) ? vy : 0.1f * vy;
            }
            *(float2*)(out + ((size_t)b * Cout_real + o0) * HWSZ + rowoff) = make_float2(vx, vy);
        }
        if (o1 < Cout_real) {
            float bv = bias[o1];
            float vx = d[nt][2] + bv, vy = d[nt][3] + bv;
            if (lrelu) {
                vx = (vx >= 0.f) ? vx : 0.1f * vx;
                vy = (vy >= 0.f) ? vy : 0.1f * vy;
            }
            *(float2*)(out + ((size_t)b * Cout_real + o1) * HWSZ + rowoff) = make_float2(vx, vy);
        }
    }
}

// ---------------------------------------------------------------------------
// Deformable conv — R4 best version (+ fast activations, verified neutral).
// ---------------------------------------------------------------------------
__global__ void __launch_bounds__(128, 4)
deform_k(const float* __restrict__ x, const float* __restrict__ o4,
         const float* __restrict__ wt, const float* __restrict__ bias,
         float* __restrict__ out) {
    const int tx = threadIdx.x, ty = threadIdx.y;
    const int tid = ty * 32 + tx;
    const int b   = blockIdx.z;
    const int px  = blockIdx.x * 32 + tx;
    const int py  = blockIdx.y * 4 + ty;
    const int p   = py * WW + px;

    __shared__ __align__(16) u64 s_w[8 * 9 * 32];

    u64 acc[32];
#pragma unroll
    for (int q = 0; q < 32; q++) acc[q] = 0ull;

    const float* xb = x + (size_t)b * CIN * HWSZ;
    const float* ob = o4 + (size_t)b * OC4 * HWSZ;

    for (int g = 0; g < DG; g++) {
        __syncthreads();
        const u64* wg = (const u64*)(wt + (size_t)g * 8 * 9 * 64);
        for (int i = tid; i < 8 * 9 * 32; i += 128) s_w[i] = wg[i];
        __syncthreads();

        const float* xg = xb + (size_t)g * 8 * HWSZ;

        for (int k = 0; k < KK; k++) {
            float dy = 10.f * fast_tanh(ob[(size_t)(g * 18 + 2 * k) * HWSZ + p]);
            float dx = 10.f * fast_tanh(ob[(size_t)(g * 18 + 2 * k + 1) * HWSZ + p]);
            float m  = fast_sigmoid(ob[(size_t)(288 + g * 9 + k) * HWSZ + p]);

            float fy = (float)py - 1.f + (float)(k / 3) + dy;
            float fx = (float)px - 1.f + (float)(k % 3) + dx;
            float y0f = floorf(fy), x0f = floorf(fx);
            float ly = fy - y0f, lx = fx - x0f;
            int y0 = (int)y0f, x0 = (int)x0f;
            int y1 = y0 + 1, x1 = x0 + 1;

            bool vy0 = (y0 >= 0) && (y0 < HH);
            bool vy1 = (y1 >= 0) && (y1 < HH);
            bool vx0 = (x0 >= 0) && (x0 < WW);
            bool vx1 = (x1 >= 0) && (x1 < WW);

            float w00 = (1.f - ly) * (1.f - lx) * ((vy0 && vx0) ? m : 0.f);
            float w01 = (1.f - ly) * lx         * ((vy0 && vx1) ? m : 0.f);
            float w10 = ly * (1.f - lx)         * ((vy1 && vx0) ? m : 0.f);
            float w11 = ly * lx                 * ((vy1 && vx1) ? m : 0.f);

            int yc0 = min(max(y0, 0), HH - 1);
            int yc1 = min(max(y1, 0), HH - 1);
            int xc0 = min(max(x0, 0), WW - 1);
            int xc1 = min(max(x1, 0), WW - 1);
            int i00 = yc0 * WW + xc0, i01 = yc0 * WW + xc1;
            int i10 = yc1 * WW + xc0, i11 = yc1 * WW + xc1;

#pragma unroll
            for (int c = 0; c < 8; c++) {
                const float* xc = xg + (size_t)c * HWSZ;
                float v = w00 * xc[i00] + w01 * xc[i01] + w10 * xc[i10] + w11 * xc[i11];
                u64 v2 = pk2(v, v);
                const ulonglong2* wp = (const ulonglong2*)&s_w[(c * 9 + k) * 32];
#pragma unroll
                for (int q = 0; q < 16; q++) {
                    ulonglong2 wq = wp[q];
                    acc[q * 2 + 0] = ffma2(v2, wq.x, acc[q * 2 + 0]);
                    acc[q * 2 + 1] = ffma2(v2, wq.y, acc[q * 2 + 1]);
                }
            }
        }
    }

    float* outb = out + (size_t)b * COUT * HWSZ + p;
#pragma unroll
    for (int q = 0; q < 32; q++) {
        float2 v = upk(acc[q]);
        outb[(size_t)(2 * q + 0) * HWSZ] = v.x + bias[2 * q + 0];
        outb[(size_t)(2 * q + 1) * HWSZ] = v.y + bias[2 * q + 1];
    }
}

// ---------------------------------------------------------------------------
// Launcher
// ---------------------------------------------------------------------------
extern "C" void kernel_launch(void* const* d_in, const int* in_sizes, int n_in,
                              void* d_out, int out_size) {
    const float* x          = (const float*)d_in[0];
    const float* extra_feat = (const float*)d_in[1];
    const float* w1 = (const float*)d_in[2];
    const float* b1 = (const float*)d_in[3];
    const float* w2 = (const float*)d_in[4];
    const float* b2 = (const float*)d_in[5];
    const float* w3 = (const float*)d_in[6];
    const float* b3 = (const float*)d_in[7];
    const float* w4 = (const float*)d_in[8];
    const float* b4 = (const float*)d_in[9];
    const float* weight = (const float*)d_in[10];
    const float* bias   = (const float*)d_in[11];
    float* out = (float*)d_out;

    float *t1, *t2, *o4, *wt;
    __nv_bfloat16 *w1h, *w1l, *w2h, *w2l, *w3h, *w3l, *w4h, *w4l;
    cudaGetSymbolAddress((void**)&t1, g_t1);
    cudaGetSymbolAddress((void**)&t2, g_t2);
    cudaGetSymbolAddress((void**)&o4, g_o4);
    cudaGetSymbolAddress((void**)&wt, g_wt);
    cudaGetSymbolAddress((void**)&w1h, g_w1h);
    cudaGetSymbolAddress((void**)&w1l, g_w1l);
    cudaGetSymbolAddress((void**)&w2h, g_w2h);
    cudaGetSymbolAddress((void**)&w2l, g_w2l);
    cudaGetSymbolAddress((void**)&w3h, g_w3h);
    cudaGetSymbolAddress((void**)&w3l, g_w3l);
    cudaGetSymbolAddress((void**)&w4h, g_w4h);
    cudaGetSymbolAddress((void**)&w4l, g_w4l);

    cudaFuncSetAttribute(conv_mma_k, cudaFuncAttributeMaxDynamicSharedMemorySize, SMEMC);

    // prep: deform weight transpose + conv weight bf16 splits
    {
        int n = CIN * KK * COUT;
        transpose_weight_k<<<(n + 255) / 256, 256>>>(weight, wt);
        int n1 = 9 * 64 * 192;
        split_w_k<<<(n1 + 255) / 256, 256>>>(w1, w1h, w1l, 64, 64, 192);
        int n2 = 9 * 64 * 64;
        split_w_k<<<(n2 + 255) / 256, 256>>>(w2, w2h, w2l, 64, 64, 64);
        split_w_k<<<(n2 + 255) / 256, 256>>>(w3, w3h, w3l, 64, 64, 64);
        int n4 = 9 * OCP4 * 64;
        split_w_k<<<(n4 + 255) / 256, 256>>>(w4, w4h, w4l, OC4, OCP4, 64);
    }

    // conv1: extra_feat (192ch) -> t1 (64ch), lrelu
    conv_mma_k<<<dim3(HH, 1, BATCH), 256, SMEMC>>>(extra_feat, w1h, w1l, b1, t1, 192, 64, 64, 1);
    // conv2: t1 -> t2, lrelu
    conv_mma_k<<<dim3(HH, 1, BATCH), 256, SMEMC>>>(t1, w2h, w2l, b2, t2, 64, 64, 64, 1);
    // conv3: t2 -> t1, lrelu
    conv_mma_k<<<dim3(HH, 1, BATCH), 256, SMEMC>>>(t2, w3h, w3l, b3, t1, 64, 64, 64, 1);
    // conv4: t1 -> o4 (432ch, +bias, no activation)
    conv_mma_k<<<dim3(HH, OCP4 / 64, BATCH), 256, SMEMC>>>(t1, w4h, w4l, b4, o4, 64, OCP4, OC4, 0);
    // deformable conv: x + o4 -> out
    deform_k<<<dim3(WW / 32, HH / 4, BATCH), dim3(32, 4)>>>(x, o4, wt, bias, out);
}